// round 15
// baseline (speedup 1.0000x reference)
#include <cuda_runtime.h>
#include <cuda_fp16.h>
#include <cstdint>

#define D_DIM 256
#define N_TOK 32768
#define N_CODE 2048

// ---------------- scratch (static device globals) ---------------------------
__device__ __half g_xhi[N_TOK * D_DIM];   // X hi split, m16n8k16 A-fragment order
__device__ __half g_xlo[N_TOK * D_DIM];   // X lo split
__device__ __half g_ehi[N_CODE * D_DIM];  // E hi split, paired B-fragment order
__device__ __half g_elo[N_CODE * D_DIM];  // E lo split
__device__ float  g_embed[N_CODE * D_DIM];// E row-major (gather)
__device__ float  g_esq[N_CODE];          // ||e||^2
__device__ unsigned long long g_key[N_TOK]; // packed (mono(dist)<<32 | code)

// ---------------- helpers ----------------------------------------------------
__device__ __forceinline__ uint32_t smem_u32(const void* p) {
    uint32_t a;
    asm("{ .reg .u64 t; cvta.to.shared.u64 t, %1; cvt.u32.u64 %0, t; }"
        : "=r"(a) : "l"(p));
    return a;
}
__device__ __forceinline__ uint32_t pack2(__half a, __half b) {
    __half2 h2 = __halves2half2(a, b);
    return *reinterpret_cast<uint32_t*>(&h2);
}
__device__ __forceinline__ uint32_t split2(float a, float b, uint32_t& lo) {
    __half ha = __float2half_rn(a);
    __half la = __float2half_rn(a - __half2float(ha));
    __half hb = __float2half_rn(b);
    __half lb = __float2half_rn(b - __half2float(hb));
    lo = pack2(la, lb);
    return pack2(ha, hb);
}
// monotone float->uint mapping (preserves total order)
__device__ __forceinline__ uint32_t fmono(float f) {
    uint32_t b = __float_as_uint(f);
    return b ^ ((b & 0x80000000u) ? 0xFFFFFFFFu : 0x80000000u);
}

#define MBAR_INIT(a, c) asm volatile("mbarrier.init.shared.b64 [%0], %1;" :: "r"(a), "r"((uint32_t)(c)) : "memory")
#define MBAR_EXPECT_TX(a, b) asm volatile("mbarrier.arrive.expect_tx.shared.b64 _, [%0], %1;" :: "r"(a), "r"((uint32_t)(b)) : "memory")
#define MBAR_ARRIVE(a)  asm volatile("mbarrier.arrive.shared.b64 _, [%0];" :: "r"(a) : "memory")

#define MBAR_WAIT(mbar, parity) do {                                          \
    uint32_t _m = (mbar), _ph = (parity), _done;                              \
    asm volatile("{ .reg .pred p; mbarrier.try_wait.parity.acquire.cta.shared::cta.b64 p, [%1], %2; selp.b32 %0, 1, 0, p; }" \
                 : "=r"(_done) : "r"(_m), "r"(_ph) : "memory");               \
    if (!_done) {                                                             \
        asm volatile("{ .reg .pred P1; WL_%=: mbarrier.try_wait.parity.acquire.cta.shared::cta.b64 P1, [%0], %1, 0x989680; @P1 bra.uni WD_%=; bra.uni WL_%=; WD_%=: }" \
                     :: "r"(_m), "r"(_ph) : "memory");                        \
    }                                                                         \
} while (0)

#define BULK_G2S(dst, src, bytes, mbar)                                       \
    asm volatile("cp.async.bulk.shared::cluster.global.mbarrier::complete_tx::bytes [%0], [%1], %2, [%3];" \
                 :: "r"(dst), "l"(src), "r"((uint32_t)(bytes)), "r"(mbar) : "memory")

// mma.sync m16n8k16 fp16 -> fp32 accumulate
__device__ __forceinline__ void mma_f16(float* d, const uint32_t* a, const uint32_t* b) {
    asm("mma.sync.aligned.m16n8k16.row.col.f32.f16.f16.f32 "
        "{%0,%1,%2,%3}, {%4,%5,%6,%7}, {%8,%9}, {%0,%1,%2,%3};"
        : "+f"(d[0]), "+f"(d[1]), "+f"(d[2]), "+f"(d[3])
        : "r"(a[0]), "r"(a[1]), "r"(a[2]), "r"(a[3]), "r"(b[0]), "r"(b[1]));
}

// ---------------------------------------------------------------------------
// Fused prep.
// Blocks [0, 1024): E prep, 2 codes per block; B fragments in PAIRED order.
// Blocks [1024, 5120): X split, register path — each thread owns one
//   (tile, ks, m_tile, lane) slot = 4 consecutive uint32 = one uint4 per
//   buffer. 4 float2 loads -> split -> 2 coalesced uint4 stores. No smem.
// ---------------------------------------------------------------------------
__global__ void __launch_bounds__(256) prep_all_kernel(const float* __restrict__ X,
                                                       const float* __restrict__ embed_sum,
                                                       const float* __restrict__ usage) {
    if (blockIdx.x < N_CODE / 2) {
        int t = threadIdx.x;
        int k = blockIdx.x * 2 + (t >> 7);
        int tl = t & 127;
        __shared__ float wsum[8];

        if (t < 32) g_key[blockIdx.x * 32 + t] = 0xFFFFFFFFFFFFFFFFull;

        float u = fmaxf(usage[k], 1e-5f);
        float2 vv = ((const float2*)embed_sum)[k * 128 + tl];
        float v0 = vv.x / u, v1 = vv.y / u;
        ((float2*)g_embed)[k * 128 + tl] = make_float2(v0, v1);

        uint32_t lo, hi = split2(v0, v1, lo);

        int d = 2 * tl;
        int pass = k >> 7, n_in = k & 127;
        int n_tile = n_in >> 3, ncol = n_in & 7;
        int ch = d >> 6, kk = d & 63, ks = kk >> 4, kc = kk & 15;
        int lane = ncol * 4 + ((kc >> 1) & 3);
        int reg = kc >> 3;
        // paired order: two adjacent n_tiles share a 16-byte lane slot
        int u32i = (pass * 4 + ch) * 4096 +
                   ((ks * 8 + (n_tile >> 1)) * 32 + lane) * 4 +
                   (n_tile & 1) * 2 + reg;
        ((uint32_t*)g_ehi)[u32i] = hi;
        ((uint32_t*)g_elo)[u32i] = lo;

        float val = v0 * v0 + v1 * v1;
        #pragma unroll
        for (int off = 16; off > 0; off >>= 1)
            val += __shfl_down_sync(0xffffffffu, val, off);
        if ((t & 31) == 0) wsum[t >> 5] = val;
        __syncthreads();
        if (tl == 0) {
            int w0 = (t >> 7) * 4;
            g_esq[k] = wsum[w0] + wsum[w0 + 1] + wsum[w0 + 2] + wsum[w0 + 3];
        }
    } else {
        // -------- X split: register path, coalesced uint4 output -------------
        int id = (blockIdx.x - N_CODE / 2) * 256 + threadIdx.x;  // 0 .. 1M-1
        int tile = id >> 10;          // (m_block, ch): tile = m_block*4 + ch
        int slot = id & 1023;         // (ks*8 + m_tile)*32 + lane
        int m_block = tile >> 2, ch = tile & 3;
        int ks = slot >> 8, m_tile = (slot >> 5) & 7, lane = slot & 31;

        int tok0 = m_block * 128 + m_tile * 16 + (lane >> 2);
        int d0 = ch * 64 + ks * 16 + 2 * (lane & 3);   // even

        const float2* Xf2 = (const float2*)X;
        // reg0: (tok0,   d0..d0+1)   reg1: (tok0+8, d0..d0+1)
        // reg2: (tok0,   d0+8..+9)   reg3: (tok0+8, d0+8..+9)
        float2 r0 = Xf2[(size_t)tok0 * 128 + (d0 >> 1)];
        float2 r1 = Xf2[(size_t)(tok0 + 8) * 128 + (d0 >> 1)];
        float2 r2 = Xf2[(size_t)tok0 * 128 + ((d0 + 8) >> 1)];
        float2 r3 = Xf2[(size_t)(tok0 + 8) * 128 + ((d0 + 8) >> 1)];

        uint4 hi, lo;
        hi.x = split2(r0.x, r0.y, lo.x);
        hi.y = split2(r1.x, r1.y, lo.y);
        hi.z = split2(r2.x, r2.y, lo.z);
        hi.w = split2(r3.x, r3.y, lo.w);

        ((uint4*)(((uint32_t*)g_xhi) + (size_t)tile * 4096))[slot] = hi;
        ((uint4*)(((uint32_t*)g_xlo) + (size_t)tile * 4096))[slot] = lo;
    }
}

// ---------------------------------------------------------------------------
// Fused fp16x2 mma.sync GEMM + argmin (paired-B loads, per-chunk A barriers).
// Grid: 1024 CTAs = 256 m-tiles x 4 quarters. 288 threads = 8 compute + 1 prod.
// A (128 KB) persistent (4 chunk barriers -> MMA starts after first 32 KB);
// B rings 3 x 32 KB. 4 passes x 128 codes, 4 chunks of k=64.
// ---------------------------------------------------------------------------
#define SMEM_TOTAL 232448
#define A_OFF 3072
#define B_OFF 134144

__global__ void __launch_bounds__(288, 1) argmin_mma_kernel() {
    extern __shared__ __align__(1024) char smem[];
    uint32_t sb = smem_u32(smem);
    int tid = threadIdx.x, lane = tid & 31, wid = tid >> 5;
    int mtile = blockIdx.x >> 2, q = blockIdx.x & 3;

    const uint32_t FB[3]  = {sb + 8,  sb + 16, sb + 24};
    const uint32_t EB[3]  = {sb + 32, sb + 40, sb + 48};
    const uint32_t AFc[4] = {sb + 56, sb + 64, sb + 72, sb + 80};
    float* esq_s = (float*)(smem + 1024);   // [512] quarter esq

    if (tid == 0) {
        #pragma unroll
        for (int c = 0; c < 4; ++c) MBAR_INIT(AFc[c], 1);
        #pragma unroll
        for (int s = 0; s < 3; ++s) { MBAR_INIT(FB[s], 1); MBAR_INIT(EB[s], 8); }
    }
    for (int i = tid; i < 512; i += 288) esq_s[i] = g_esq[q * 512 + i];
    __syncthreads();

    int row0 = mtile * 128;

    if (wid == 8) {
        // ---------------- dedicated producer warp ---------------------------
        if (lane == 0) {
            #pragma unroll
            for (int ch = 0; ch < 4; ++ch) {
                MBAR_EXPECT_TX(AFc[ch], 32768);
                BULK_G2S(sb + A_OFF + ch * 32768,
                         &g_xhi[(mtile * 4 + ch) * 8192], 16384, AFc[ch]);
                BULK_G2S(sb + A_OFF + ch * 32768 + 16384,
                         &g_xlo[(mtile * 4 + ch) * 8192], 16384, AFc[ch]);
            }
            #pragma unroll 1
            for (int g = 0; g < 16; ++g) {
                int s = g % 3;
                if (g >= 3) MBAR_WAIT(EB[s], ((g / 3) + 1) & 1);
                int pass = g >> 2, ch = g & 3;
                uint32_t st = sb + B_OFF + s * 32768;
                MBAR_EXPECT_TX(FB[s], 32768);
                BULK_G2S(st,         &g_ehi[((q * 4 + pass) * 4 + ch) * 8192], 16384, FB[s]);
                BULK_G2S(st + 16384, &g_elo[((q * 4 + pass) * 4 + ch) * 8192], 16384, FB[s]);
            }
        }
    } else {
        // ---------------- 8 compute warps ------------------------------------
        int warp_m = wid & 3, warp_n = wid >> 2;
        int t4 = lane & 3, g4 = lane >> 2;

        float best[2][2];
        int bestI[2][2];
        #pragma unroll
        for (int a = 0; a < 2; ++a)
            #pragma unroll
            for (int b = 0; b < 2; ++b) { best[a][b] = 3.4e38f; bestI[a][b] = 0; }

        #pragma unroll 1
        for (int pass = 0; pass < 4; ++pass) {
            float acc[2][8][4];
            #pragma unroll
            for (int mt = 0; mt < 2; ++mt)
                #pragma unroll
                for (int nt = 0; nt < 8; ++nt)
                    #pragma unroll
                    for (int j = 0; j < 4; ++j) acc[mt][nt][j] = 0.f;

            #pragma unroll 1
            for (int ch = 0; ch < 4; ++ch) {
                int g = pass * 4 + ch;
                int s = g % 3;
                MBAR_WAIT(FB[s], (g / 3) & 1);
                if (pass == 0) MBAR_WAIT(AFc[ch], 0);   // A chunk ready

                const char* Ah = smem + A_OFF + ch * 32768;
                const char* Al = Ah + 16384;
                const char* Bh = smem + B_OFF + s * 32768;
                const char* Bl = Bh + 16384;

                #pragma unroll
                for (int ks = 0; ks < 4; ++ks) {
                    uint32_t ah[2][4], al[2][4];
                    #pragma unroll
                    for (int mt = 0; mt < 2; ++mt) {
                        int off = ((ks * 8 + warp_m * 2 + mt) * 32 + lane) * 16;
                        *(uint4*)ah[mt] = *(const uint4*)(Ah + off);
                        *(uint4*)al[mt] = *(const uint4*)(Al + off);
                    }
                    // paired B loads: one uint4 covers two adjacent nt
                    uint32_t bh[8][2], bl[8][2];
                    #pragma unroll
                    for (int p = 0; p < 4; ++p) {
                        int off = ((ks * 8 + warp_n * 4 + p) * 32 + lane) * 16;
                        uint4 th = *(const uint4*)(Bh + off);
                        uint4 tl_ = *(const uint4*)(Bl + off);
                        bh[2 * p][0] = th.x; bh[2 * p][1] = th.y;
                        bh[2 * p + 1][0] = th.z; bh[2 * p + 1][1] = th.w;
                        bl[2 * p][0] = tl_.x; bl[2 * p][1] = tl_.y;
                        bl[2 * p + 1][0] = tl_.z; bl[2 * p + 1][1] = tl_.w;
                    }
                    // term-ordered: hi*hi, hi*lo, lo*hi
                    #pragma unroll
                    for (int mt = 0; mt < 2; ++mt)
                        #pragma unroll
                        for (int nt = 0; nt < 8; ++nt)
                            mma_f16(acc[mt][nt], ah[mt], bh[nt]);
                    #pragma unroll
                    for (int mt = 0; mt < 2; ++mt)
                        #pragma unroll
                        for (int nt = 0; nt < 8; ++nt)
                            mma_f16(acc[mt][nt], ah[mt], bl[nt]);
                    #pragma unroll
                    for (int mt = 0; mt < 2; ++mt)
                        #pragma unroll
                        for (int nt = 0; nt < 8; ++nt)
                            mma_f16(acc[mt][nt], al[mt], bh[nt]);
                }
                if (lane == 0) MBAR_ARRIVE(EB[s]);
            }

            // fold pass into running argmin: dist = esq - 2*dot
            #pragma unroll
            for (int nt = 0; nt < 8; ++nt) {
                int clocal = pass * 128 + warp_n * 64 + nt * 8 + 2 * t4;
                float e0 = esq_s[clocal], e1 = esq_s[clocal + 1];
                int cbase = q * 512 + clocal;
                #pragma unroll
                for (int mt = 0; mt < 2; ++mt) {
                    float d0v = fmaf(-2.f, acc[mt][nt][0], e0);
                    if (d0v < best[mt][0]) { best[mt][0] = d0v; bestI[mt][0] = cbase; }
                    float d1v = fmaf(-2.f, acc[mt][nt][1], e1);
                    if (d1v < best[mt][0]) { best[mt][0] = d1v; bestI[mt][0] = cbase + 1; }
                    float d2v = fmaf(-2.f, acc[mt][nt][2], e0);
                    if (d2v < best[mt][1]) { best[mt][1] = d2v; bestI[mt][1] = cbase; }
                    float d3v = fmaf(-2.f, acc[mt][nt][3], e1);
                    if (d3v < best[mt][1]) { best[mt][1] = d3v; bestI[mt][1] = cbase + 1; }
                }
            }
        }

        // width-4 shuffle reduce, then global atomic merge
        #pragma unroll
        for (int mt = 0; mt < 2; ++mt)
            #pragma unroll
            for (int h = 0; h < 2; ++h) {
                float b = best[mt][h];
                int bi = bestI[mt][h];
                #pragma unroll
                for (int off = 2; off > 0; off >>= 1) {
                    float ob = __shfl_down_sync(0xffffffffu, b, off, 4);
                    int obi = __shfl_down_sync(0xffffffffu, bi, off, 4);
                    if (ob < b || (ob == b && obi < bi)) { b = ob; bi = obi; }
                }
                if (t4 == 0) {
                    int tok = row0 + warp_m * 32 + mt * 16 + g4 + 8 * h;
                    unsigned long long key =
                        ((unsigned long long)fmono(b) << 32) | (uint32_t)bi;
                    atomicMin(&g_key[tok], key);
                }
            }
    }
}

// ---------------------------------------------------------------------------
// gather: two (token, float4 chunk) elements per thread (ILP 2).
// 4096 CTAs x 256 threads.
// ---------------------------------------------------------------------------
__global__ void __launch_bounds__(256) gather_kernel(float* __restrict__ out, int N) {
    int i0 = blockIdx.x * 512 + threadIdx.x;
    int i1 = i0 + 256;
    int tok0 = i0 >> 6, c40 = i0 & 63;
    int tok1 = i1 >> 6, c41 = i1 & 63;
    int idx0 = (int)(g_key[tok0] & 0xFFFFFFFFull);
    int idx1 = (int)(g_key[tok1] & 0xFFFFFFFFull);
    float4 v0 = ((const float4*)g_embed)[(size_t)idx0 * 64 + c40];
    float4 v1 = ((const float4*)g_embed)[(size_t)idx1 * 64 + c41];
    ((float4*)out)[i0] = v0;
    ((float4*)out)[i1] = v1;
    if (c40 == 0) out[(size_t)N * D_DIM + tok0] = (float)idx0;
    if (c41 == 0) out[(size_t)N * D_DIM + tok1] = (float)idx1;
}

// ---------------------------------------------------------------------------
extern "C" void kernel_launch(void* const* d_in, const int* in_sizes, int n_in,
                              void* d_out, int out_size) {
    const float* X  = (const float*)d_in[0];
    const float* ES = (const float*)d_in[1];
    const float* U  = (const float*)d_in[2];
    float* out = (float*)d_out;
    (void)n_in; (void)out_size;
    int N = in_sizes[0] / D_DIM;   // 32768

    cudaFuncSetAttribute(argmin_mma_kernel,
                         cudaFuncAttributeMaxDynamicSharedMemorySize, SMEM_TOTAL);

    prep_all_kernel<<<N_CODE / 2 + (N / 128) * 16, 256>>>(X, ES, U);
    argmin_mma_kernel<<<(N / 128) * 4, 288, SMEM_TOTAL>>>();
    gather_kernel<<<(N * 64) / 512, 256>>>(out, N);
}

// round 16
// speedup vs baseline: 1.0153x; 1.0153x over previous
#include <cuda_runtime.h>
#include <cuda_fp16.h>
#include <cstdint>

#define D_DIM 256
#define N_TOK 32768
#define N_CODE 2048

// ---------------- scratch (static device globals) ---------------------------
__device__ __half g_xhi[N_TOK * D_DIM];   // X hi split, m16n8k16 A-fragment order
__device__ __half g_xlo[N_TOK * D_DIM];   // X lo split
__device__ __half g_ehi[N_CODE * D_DIM];  // E hi split, paired B-fragment order
__device__ __half g_elo[N_CODE * D_DIM];  // E lo split
__device__ float  g_embed[N_CODE * D_DIM];// E row-major (gather)
__device__ float  g_esq[N_CODE];          // ||e||^2
__device__ unsigned long long g_key[N_TOK]; // packed (mono(dist)<<32 | code)

// ---------------- helpers ----------------------------------------------------
__device__ __forceinline__ uint32_t smem_u32(const void* p) {
    uint32_t a;
    asm("{ .reg .u64 t; cvta.to.shared.u64 t, %1; cvt.u32.u64 %0, t; }"
        : "=r"(a) : "l"(p));
    return a;
}
__device__ __forceinline__ uint32_t pack2(__half a, __half b) {
    __half2 h2 = __halves2half2(a, b);
    return *reinterpret_cast<uint32_t*>(&h2);
}
__device__ __forceinline__ uint32_t split2(float a, float b, uint32_t& lo) {
    __half ha = __float2half_rn(a);
    __half la = __float2half_rn(a - __half2float(ha));
    __half hb = __float2half_rn(b);
    __half lb = __float2half_rn(b - __half2float(hb));
    lo = pack2(la, lb);
    return pack2(ha, hb);
}
// monotone float->uint mapping (preserves total order)
__device__ __forceinline__ uint32_t fmono(float f) {
    uint32_t b = __float_as_uint(f);
    return b ^ ((b & 0x80000000u) ? 0xFFFFFFFFu : 0x80000000u);
}

#define MBAR_INIT(a, c) asm volatile("mbarrier.init.shared.b64 [%0], %1;" :: "r"(a), "r"((uint32_t)(c)) : "memory")
#define MBAR_EXPECT_TX(a, b) asm volatile("mbarrier.arrive.expect_tx.shared.b64 _, [%0], %1;" :: "r"(a), "r"((uint32_t)(b)) : "memory")
#define MBAR_ARRIVE(a)  asm volatile("mbarrier.arrive.shared.b64 _, [%0];" :: "r"(a) : "memory")

#define MBAR_WAIT(mbar, parity) do {                                          \
    uint32_t _m = (mbar), _ph = (parity), _done;                              \
    asm volatile("{ .reg .pred p; mbarrier.try_wait.parity.acquire.cta.shared::cta.b64 p, [%1], %2; selp.b32 %0, 1, 0, p; }" \
                 : "=r"(_done) : "r"(_m), "r"(_ph) : "memory");               \
    if (!_done) {                                                             \
        asm volatile("{ .reg .pred P1; WL_%=: mbarrier.try_wait.parity.acquire.cta.shared::cta.b64 P1, [%0], %1, 0x989680; @P1 bra.uni WD_%=; bra.uni WL_%=; WD_%=: }" \
                     :: "r"(_m), "r"(_ph) : "memory");                        \
    }                                                                         \
} while (0)

#define BULK_G2S(dst, src, bytes, mbar)                                       \
    asm volatile("cp.async.bulk.shared::cluster.global.mbarrier::complete_tx::bytes [%0], [%1], %2, [%3];" \
                 :: "r"(dst), "l"(src), "r"((uint32_t)(bytes)), "r"(mbar) : "memory")

// mma.sync m16n8k16 fp16 -> fp32 accumulate
__device__ __forceinline__ void mma_f16(float* d, const uint32_t* a, const uint32_t* b) {
    asm("mma.sync.aligned.m16n8k16.row.col.f32.f16.f16.f32 "
        "{%0,%1,%2,%3}, {%4,%5,%6,%7}, {%8,%9}, {%0,%1,%2,%3};"
        : "+f"(d[0]), "+f"(d[1]), "+f"(d[2]), "+f"(d[3])
        : "r"(a[0]), "r"(a[1]), "r"(a[2]), "r"(a[3]), "r"(b[0]), "r"(b[1]));
}

// ---------------------------------------------------------------------------
// Fused prep (R15 version — measured 12.5 us).
// Blocks [0, 1024): E prep, 2 codes per block; B fragments in PAIRED order.
// Blocks [1024, 5120): X split, register path — each thread owns one
//   (tile, ks, m_tile, lane) slot = one uint4 per buffer. No smem.
// ---------------------------------------------------------------------------
__global__ void __launch_bounds__(256) prep_all_kernel(const float* __restrict__ X,
                                                       const float* __restrict__ embed_sum,
                                                       const float* __restrict__ usage) {
    if (blockIdx.x < N_CODE / 2) {
        int t = threadIdx.x;
        int k = blockIdx.x * 2 + (t >> 7);
        int tl = t & 127;
        __shared__ float wsum[8];

        if (t < 32) g_key[blockIdx.x * 32 + t] = 0xFFFFFFFFFFFFFFFFull;

        float u = fmaxf(usage[k], 1e-5f);
        float2 vv = ((const float2*)embed_sum)[k * 128 + tl];
        float v0 = vv.x / u, v1 = vv.y / u;
        ((float2*)g_embed)[k * 128 + tl] = make_float2(v0, v1);

        uint32_t lo, hi = split2(v0, v1, lo);

        int d = 2 * tl;
        int pass = k >> 7, n_in = k & 127;
        int n_tile = n_in >> 3, ncol = n_in & 7;
        int ch = d >> 6, kk = d & 63, ks = kk >> 4, kc = kk & 15;
        int lane = ncol * 4 + ((kc >> 1) & 3);
        int reg = kc >> 3;
        // paired order: two adjacent n_tiles share a 16-byte lane slot
        int u32i = (pass * 4 + ch) * 4096 +
                   ((ks * 8 + (n_tile >> 1)) * 32 + lane) * 4 +
                   (n_tile & 1) * 2 + reg;
        ((uint32_t*)g_ehi)[u32i] = hi;
        ((uint32_t*)g_elo)[u32i] = lo;

        float val = v0 * v0 + v1 * v1;
        #pragma unroll
        for (int off = 16; off > 0; off >>= 1)
            val += __shfl_down_sync(0xffffffffu, val, off);
        if ((t & 31) == 0) wsum[t >> 5] = val;
        __syncthreads();
        if (tl == 0) {
            int w0 = (t >> 7) * 4;
            g_esq[k] = wsum[w0] + wsum[w0 + 1] + wsum[w0 + 2] + wsum[w0 + 3];
        }
    } else {
        // -------- X split: register path, coalesced uint4 output -------------
        int id = (blockIdx.x - N_CODE / 2) * 256 + threadIdx.x;  // 0 .. 1M-1
        int tile = id >> 10;          // (m_block, ch): tile = m_block*4 + ch
        int slot = id & 1023;         // (ks*8 + m_tile)*32 + lane
        int m_block = tile >> 2, ch = tile & 3;
        int ks = slot >> 8, m_tile = (slot >> 5) & 7, lane = slot & 31;

        int tok0 = m_block * 128 + m_tile * 16 + (lane >> 2);
        int d0 = ch * 64 + ks * 16 + 2 * (lane & 3);   // even

        const float2* Xf2 = (const float2*)X;
        float2 r0 = Xf2[(size_t)tok0 * 128 + (d0 >> 1)];
        float2 r1 = Xf2[(size_t)(tok0 + 8) * 128 + (d0 >> 1)];
        float2 r2 = Xf2[(size_t)tok0 * 128 + ((d0 + 8) >> 1)];
        float2 r3 = Xf2[(size_t)(tok0 + 8) * 128 + ((d0 + 8) >> 1)];

        uint4 hi, lo;
        hi.x = split2(r0.x, r0.y, lo.x);
        hi.y = split2(r1.x, r1.y, lo.y);
        hi.z = split2(r2.x, r2.y, lo.z);
        hi.w = split2(r3.x, r3.y, lo.w);

        ((uint4*)(((uint32_t*)g_xhi) + (size_t)tile * 4096))[slot] = hi;
        ((uint4*)(((uint32_t*)g_xlo) + (size_t)tile * 4096))[slot] = lo;
    }
}

// ---------------------------------------------------------------------------
// Fused fp16x2 mma.sync GEMM + argmin (exact R14 body: single A barrier,
// paired-B loads). Grid 1024 = 256 m-tiles x 4 quarters; 288 threads.
// A (128 KB) persistent; B rings 3 x 32 KB. 4 passes x 128 codes, 4 chunks.
// ---------------------------------------------------------------------------
#define SMEM_TOTAL 232448
#define A_OFF 3072
#define B_OFF 134144

__global__ void __launch_bounds__(288, 1) argmin_mma_kernel() {
    extern __shared__ __align__(1024) char smem[];
    uint32_t sb = smem_u32(smem);
    int tid = threadIdx.x, lane = tid & 31, wid = tid >> 5;
    int mtile = blockIdx.x >> 2, q = blockIdx.x & 3;

    const uint32_t AF    = sb + 0;
    const uint32_t FB[3] = {sb + 8,  sb + 16, sb + 24};
    const uint32_t EB[3] = {sb + 32, sb + 40, sb + 48};
    float* esq_s = (float*)(smem + 1024);   // [512] quarter esq

    if (tid == 0) {
        MBAR_INIT(AF, 1);
        #pragma unroll
        for (int s = 0; s < 3; ++s) { MBAR_INIT(FB[s], 1); MBAR_INIT(EB[s], 8); }
    }
    for (int i = tid; i < 512; i += 288) esq_s[i] = g_esq[q * 512 + i];
    __syncthreads();

    int row0 = mtile * 128;

    if (wid == 8) {
        // ---------------- dedicated producer warp ---------------------------
        if (lane == 0) {
            MBAR_EXPECT_TX(AF, 131072);
            #pragma unroll
            for (int ch = 0; ch < 4; ++ch) {
                BULK_G2S(sb + A_OFF + ch * 32768,
                         &g_xhi[(mtile * 4 + ch) * 8192], 16384, AF);
                BULK_G2S(sb + A_OFF + ch * 32768 + 16384,
                         &g_xlo[(mtile * 4 + ch) * 8192], 16384, AF);
            }
            #pragma unroll 1
            for (int g = 0; g < 16; ++g) {
                int s = g % 3;
                if (g >= 3) MBAR_WAIT(EB[s], ((g / 3) + 1) & 1);
                int pass = g >> 2, ch = g & 3;
                uint32_t st = sb + B_OFF + s * 32768;
                MBAR_EXPECT_TX(FB[s], 32768);
                BULK_G2S(st,         &g_ehi[((q * 4 + pass) * 4 + ch) * 8192], 16384, FB[s]);
                BULK_G2S(st + 16384, &g_elo[((q * 4 + pass) * 4 + ch) * 8192], 16384, FB[s]);
            }
        }
    } else {
        // ---------------- 8 compute warps ------------------------------------
        int warp_m = wid & 3, warp_n = wid >> 2;
        int t4 = lane & 3, g4 = lane >> 2;

        float best[2][2];
        int bestI[2][2];
        #pragma unroll
        for (int a = 0; a < 2; ++a)
            #pragma unroll
            for (int b = 0; b < 2; ++b) { best[a][b] = 3.4e38f; bestI[a][b] = 0; }

        MBAR_WAIT(AF, 0);   // A resident for whole kernel

        #pragma unroll 1
        for (int pass = 0; pass < 4; ++pass) {
            float acc[2][8][4];
            #pragma unroll
            for (int mt = 0; mt < 2; ++mt)
                #pragma unroll
                for (int nt = 0; nt < 8; ++nt)
                    #pragma unroll
                    for (int j = 0; j < 4; ++j) acc[mt][nt][j] = 0.f;

            #pragma unroll 1
            for (int ch = 0; ch < 4; ++ch) {
                int g = pass * 4 + ch;
                int s = g % 3;
                MBAR_WAIT(FB[s], (g / 3) & 1);

                const char* Ah = smem + A_OFF + ch * 32768;
                const char* Al = Ah + 16384;
                const char* Bh = smem + B_OFF + s * 32768;
                const char* Bl = Bh + 16384;

                #pragma unroll
                for (int ks = 0; ks < 4; ++ks) {
                    uint32_t ah[2][4], al[2][4];
                    #pragma unroll
                    for (int mt = 0; mt < 2; ++mt) {
                        int off = ((ks * 8 + warp_m * 2 + mt) * 32 + lane) * 16;
                        *(uint4*)ah[mt] = *(const uint4*)(Ah + off);
                        *(uint4*)al[mt] = *(const uint4*)(Al + off);
                    }
                    // paired B loads: one uint4 covers two adjacent nt
                    uint32_t bh[8][2], bl[8][2];
                    #pragma unroll
                    for (int p = 0; p < 4; ++p) {
                        int off = ((ks * 8 + warp_n * 4 + p) * 32 + lane) * 16;
                        uint4 th = *(const uint4*)(Bh + off);
                        uint4 tl_ = *(const uint4*)(Bl + off);
                        bh[2 * p][0] = th.x; bh[2 * p][1] = th.y;
                        bh[2 * p + 1][0] = th.z; bh[2 * p + 1][1] = th.w;
                        bl[2 * p][0] = tl_.x; bl[2 * p][1] = tl_.y;
                        bl[2 * p + 1][0] = tl_.z; bl[2 * p + 1][1] = tl_.w;
                    }
                    // term-ordered: hi*hi, hi*lo, lo*hi
                    #pragma unroll
                    for (int mt = 0; mt < 2; ++mt)
                        #pragma unroll
                        for (int nt = 0; nt < 8; ++nt)
                            mma_f16(acc[mt][nt], ah[mt], bh[nt]);
                    #pragma unroll
                    for (int mt = 0; mt < 2; ++mt)
                        #pragma unroll
                        for (int nt = 0; nt < 8; ++nt)
                            mma_f16(acc[mt][nt], ah[mt], bl[nt]);
                    #pragma unroll
                    for (int mt = 0; mt < 2; ++mt)
                        #pragma unroll
                        for (int nt = 0; nt < 8; ++nt)
                            mma_f16(acc[mt][nt], al[mt], bh[nt]);
                }
                if (lane == 0) MBAR_ARRIVE(EB[s]);
            }

            // fold pass into running argmin: dist = esq - 2*dot
            #pragma unroll
            for (int nt = 0; nt < 8; ++nt) {
                int clocal = pass * 128 + warp_n * 64 + nt * 8 + 2 * t4;
                float e0 = esq_s[clocal], e1 = esq_s[clocal + 1];
                int cbase = q * 512 + clocal;
                #pragma unroll
                for (int mt = 0; mt < 2; ++mt) {
                    float d0v = fmaf(-2.f, acc[mt][nt][0], e0);
                    if (d0v < best[mt][0]) { best[mt][0] = d0v; bestI[mt][0] = cbase; }
                    float d1v = fmaf(-2.f, acc[mt][nt][1], e1);
                    if (d1v < best[mt][0]) { best[mt][0] = d1v; bestI[mt][0] = cbase + 1; }
                    float d2v = fmaf(-2.f, acc[mt][nt][2], e0);
                    if (d2v < best[mt][1]) { best[mt][1] = d2v; bestI[mt][1] = cbase; }
                    float d3v = fmaf(-2.f, acc[mt][nt][3], e1);
                    if (d3v < best[mt][1]) { best[mt][1] = d3v; bestI[mt][1] = cbase + 1; }
                }
            }
        }

        // width-4 shuffle reduce, then global atomic merge
        #pragma unroll
        for (int mt = 0; mt < 2; ++mt)
            #pragma unroll
            for (int h = 0; h < 2; ++h) {
                float b = best[mt][h];
                int bi = bestI[mt][h];
                #pragma unroll
                for (int off = 2; off > 0; off >>= 1) {
                    float ob = __shfl_down_sync(0xffffffffu, b, off, 4);
                    int obi = __shfl_down_sync(0xffffffffu, bi, off, 4);
                    if (ob < b || (ob == b && obi < bi)) { b = ob; bi = obi; }
                }
                if (t4 == 0) {
                    int tok = row0 + warp_m * 32 + mt * 16 + g4 + 8 * h;
                    unsigned long long key =
                        ((unsigned long long)fmono(b) << 32) | (uint32_t)bi;
                    atomicMin(&g_key[tok], key);
                }
            }
    }
}

// ---------------------------------------------------------------------------
// gather: two (token, float4 chunk) elements per thread (ILP 2).
// 4096 CTAs x 256 threads.
// ---------------------------------------------------------------------------
__global__ void __launch_bounds__(256) gather_kernel(float* __restrict__ out, int N) {
    int i0 = blockIdx.x * 512 + threadIdx.x;
    int i1 = i0 + 256;
    int tok0 = i0 >> 6, c40 = i0 & 63;
    int tok1 = i1 >> 6, c41 = i1 & 63;
    int idx0 = (int)(g_key[tok0] & 0xFFFFFFFFull);
    int idx1 = (int)(g_key[tok1] & 0xFFFFFFFFull);
    float4 v0 = ((const float4*)g_embed)[(size_t)idx0 * 64 + c40];
    float4 v1 = ((const float4*)g_embed)[(size_t)idx1 * 64 + c41];
    ((float4*)out)[i0] = v0;
    ((float4*)out)[i1] = v1;
    if (c40 == 0) out[(size_t)N * D_DIM + tok0] = (float)idx0;
    if (c41 == 0) out[(size_t)N * D_DIM + tok1] = (float)idx1;
}

// ---------------------------------------------------------------------------
extern "C" void kernel_launch(void* const* d_in, const int* in_sizes, int n_in,
                              void* d_out, int out_size) {
    const float* X  = (const float*)d_in[0];
    const float* ES = (const float*)d_in[1];
    const float* U  = (const float*)d_in[2];
    float* out = (float*)d_out;
    (void)n_in; (void)out_size;
    int N = in_sizes[0] / D_DIM;   // 32768

    cudaFuncSetAttribute(argmin_mma_kernel,
                         cudaFuncAttributeMaxDynamicSharedMemorySize, SMEM_TOTAL);

    prep_all_kernel<<<N_CODE / 2 + (N / 128) * 16, 256>>>(X, ES, U);
    argmin_mma_kernel<<<(N / 128) * 4, 288, SMEM_TOTAL>>>();
    gather_kernel<<<(N * 64) / 512, 256>>>(out, N);
}

// round 17
// speedup vs baseline: 1.0157x; 1.0004x over previous
#include <cuda_runtime.h>
#include <cuda_fp16.h>
#include <cstdint>

#define D_DIM 256
#define N_TOK 32768
#define N_CODE 2048

// ---------------- scratch (static device globals) ---------------------------
__device__ __half g_xhi[N_TOK * D_DIM];   // X hi split, m16n8k16 A-fragment order
__device__ __half g_xlo[N_TOK * D_DIM];   // X lo split
__device__ __half g_ehi[N_CODE * D_DIM];  // E hi split, paired B-fragment order
__device__ __half g_elo[N_CODE * D_DIM];  // E lo split
__device__ float  g_embed[N_CODE * D_DIM];// E row-major (gather)
__device__ float  g_esq[N_CODE];          // ||e||^2
__device__ unsigned long long g_key[N_TOK]; // packed (mono(dist)<<32 | code)

// ---------------- helpers ----------------------------------------------------
__device__ __forceinline__ uint32_t smem_u32(const void* p) {
    uint32_t a;
    asm("{ .reg .u64 t; cvta.to.shared.u64 t, %1; cvt.u32.u64 %0, t; }"
        : "=r"(a) : "l"(p));
    return a;
}
__device__ __forceinline__ uint32_t pack2(__half a, __half b) {
    __half2 h2 = __halves2half2(a, b);
    return *reinterpret_cast<uint32_t*>(&h2);
}
__device__ __forceinline__ uint32_t split2(float a, float b, uint32_t& lo) {
    __half ha = __float2half_rn(a);
    __half la = __float2half_rn(a - __half2float(ha));
    __half hb = __float2half_rn(b);
    __half lb = __float2half_rn(b - __half2float(hb));
    lo = pack2(la, lb);
    return pack2(ha, hb);
}
// monotone float->uint mapping (preserves total order)
__device__ __forceinline__ uint32_t fmono(float f) {
    uint32_t b = __float_as_uint(f);
    return b ^ ((b & 0x80000000u) ? 0xFFFFFFFFu : 0x80000000u);
}

#define MBAR_INIT(a, c) asm volatile("mbarrier.init.shared.b64 [%0], %1;" :: "r"(a), "r"((uint32_t)(c)) : "memory")
#define MBAR_EXPECT_TX(a, b) asm volatile("mbarrier.arrive.expect_tx.shared.b64 _, [%0], %1;" :: "r"(a), "r"((uint32_t)(b)) : "memory")
#define MBAR_ARRIVE(a)  asm volatile("mbarrier.arrive.shared.b64 _, [%0];" :: "r"(a) : "memory")

#define MBAR_WAIT(mbar, parity) do {                                          \
    uint32_t _m = (mbar), _ph = (parity), _done;                              \
    asm volatile("{ .reg .pred p; mbarrier.try_wait.parity.acquire.cta.shared::cta.b64 p, [%1], %2; selp.b32 %0, 1, 0, p; }" \
                 : "=r"(_done) : "r"(_m), "r"(_ph) : "memory");               \
    if (!_done) {                                                             \
        asm volatile("{ .reg .pred P1; WL_%=: mbarrier.try_wait.parity.acquire.cta.shared::cta.b64 P1, [%0], %1, 0x989680; @P1 bra.uni WD_%=; bra.uni WL_%=; WD_%=: }" \
                     :: "r"(_m), "r"(_ph) : "memory");                        \
    }                                                                         \
} while (0)

#define BULK_G2S(dst, src, bytes, mbar)                                       \
    asm volatile("cp.async.bulk.shared::cluster.global.mbarrier::complete_tx::bytes [%0], [%1], %2, [%3];" \
                 :: "r"(dst), "l"(src), "r"((uint32_t)(bytes)), "r"(mbar) : "memory")

// mma.sync m16n8k16 fp16 -> fp32 accumulate
__device__ __forceinline__ void mma_f16(float* d, const uint32_t* a, const uint32_t* b) {
    asm("mma.sync.aligned.m16n8k16.row.col.f32.f16.f16.f32 "
        "{%0,%1,%2,%3}, {%4,%5,%6,%7}, {%8,%9}, {%0,%1,%2,%3};"
        : "+f"(d[0]), "+f"(d[1]), "+f"(d[2]), "+f"(d[3])
        : "r"(a[0]), "r"(a[1]), "r"(a[2]), "r"(a[3]), "r"(b[0]), "r"(b[1]));
}

// ---------------------------------------------------------------------------
// Fused prep (R15/R16 version — measured 12.5-13 us).
// Blocks [0, 1024): E prep, 2 codes per block; B fragments in PAIRED order.
// Blocks [1024, 5120): X split, register path — each thread owns one
//   (tile, ks, m_tile, lane) slot = one uint4 per buffer. No smem.
// ---------------------------------------------------------------------------
__global__ void __launch_bounds__(256) prep_all_kernel(const float* __restrict__ X,
                                                       const float* __restrict__ embed_sum,
                                                       const float* __restrict__ usage) {
    if (blockIdx.x < N_CODE / 2) {
        int t = threadIdx.x;
        int k = blockIdx.x * 2 + (t >> 7);
        int tl = t & 127;
        __shared__ float wsum[8];

        if (t < 32) g_key[blockIdx.x * 32 + t] = 0xFFFFFFFFFFFFFFFFull;

        float u = fmaxf(usage[k], 1e-5f);
        float2 vv = ((const float2*)embed_sum)[k * 128 + tl];
        float v0 = vv.x / u, v1 = vv.y / u;
        ((float2*)g_embed)[k * 128 + tl] = make_float2(v0, v1);

        uint32_t lo, hi = split2(v0, v1, lo);

        int d = 2 * tl;
        int pass = k >> 7, n_in = k & 127;
        int n_tile = n_in >> 3, ncol = n_in & 7;
        int ch = d >> 6, kk = d & 63, ks = kk >> 4, kc = kk & 15;
        int lane = ncol * 4 + ((kc >> 1) & 3);
        int reg = kc >> 3;
        // paired order: two adjacent n_tiles share a 16-byte lane slot
        int u32i = (pass * 4 + ch) * 4096 +
                   ((ks * 8 + (n_tile >> 1)) * 32 + lane) * 4 +
                   (n_tile & 1) * 2 + reg;
        ((uint32_t*)g_ehi)[u32i] = hi;
        ((uint32_t*)g_elo)[u32i] = lo;

        float val = v0 * v0 + v1 * v1;
        #pragma unroll
        for (int off = 16; off > 0; off >>= 1)
            val += __shfl_down_sync(0xffffffffu, val, off);
        if ((t & 31) == 0) wsum[t >> 5] = val;
        __syncthreads();
        if (tl == 0) {
            int w0 = (t >> 7) * 4;
            g_esq[k] = wsum[w0] + wsum[w0 + 1] + wsum[w0 + 2] + wsum[w0 + 3];
        }
    } else {
        // -------- X split: register path, coalesced uint4 output -------------
        int id = (blockIdx.x - N_CODE / 2) * 256 + threadIdx.x;  // 0 .. 1M-1
        int tile = id >> 10;          // (m_block, ch): tile = m_block*4 + ch
        int slot = id & 1023;         // (ks*8 + m_tile)*32 + lane
        int m_block = tile >> 2, ch = tile & 3;
        int ks = slot >> 8, m_tile = (slot >> 5) & 7, lane = slot & 31;

        int tok0 = m_block * 128 + m_tile * 16 + (lane >> 2);
        int d0 = ch * 64 + ks * 16 + 2 * (lane & 3);   // even

        const float2* Xf2 = (const float2*)X;
        float2 r0 = Xf2[(size_t)tok0 * 128 + (d0 >> 1)];
        float2 r1 = Xf2[(size_t)(tok0 + 8) * 128 + (d0 >> 1)];
        float2 r2 = Xf2[(size_t)tok0 * 128 + ((d0 + 8) >> 1)];
        float2 r3 = Xf2[(size_t)(tok0 + 8) * 128 + ((d0 + 8) >> 1)];

        uint4 hi, lo;
        hi.x = split2(r0.x, r0.y, lo.x);
        hi.y = split2(r1.x, r1.y, lo.y);
        hi.z = split2(r2.x, r2.y, lo.z);
        hi.w = split2(r3.x, r3.y, lo.w);

        ((uint4*)(((uint32_t*)g_xhi) + (size_t)tile * 4096))[slot] = hi;
        ((uint4*)(((uint32_t*)g_xlo) + (size_t)tile * 4096))[slot] = lo;
    }
}

// ---------------------------------------------------------------------------
// Fused fp16x2 mma.sync GEMM + argmin (R16 body + 2-barrier A prologue and
// interleaved producer queue: A-half0, B0, A-half1, B1, ...).
// Grid 1024 = 256 m-tiles x 4 quarters; 288 threads = 8 compute + 1 producer.
// A (128 KB) persistent; B rings 3 x 32 KB. 4 passes x 128 codes, 4 chunks.
// ---------------------------------------------------------------------------
#define SMEM_TOTAL 232448
#define A_OFF 3072
#define B_OFF 134144

__global__ void __launch_bounds__(288, 1) argmin_mma_kernel() {
    extern __shared__ __align__(1024) char smem[];
    uint32_t sb = smem_u32(smem);
    int tid = threadIdx.x, lane = tid & 31, wid = tid >> 5;
    int mtile = blockIdx.x >> 2, q = blockIdx.x & 3;

    const uint32_t AF0   = sb + 0;
    const uint32_t AF1   = sb + 56;
    const uint32_t FB[3] = {sb + 8,  sb + 16, sb + 24};
    const uint32_t EB[3] = {sb + 32, sb + 40, sb + 48};
    float* esq_s = (float*)(smem + 1024);   // [512] quarter esq

    if (tid == 0) {
        MBAR_INIT(AF0, 1); MBAR_INIT(AF1, 1);
        #pragma unroll
        for (int s = 0; s < 3; ++s) { MBAR_INIT(FB[s], 1); MBAR_INIT(EB[s], 8); }
    }
    for (int i = tid; i < 512; i += 288) esq_s[i] = g_esq[q * 512 + i];
    __syncthreads();

    int row0 = mtile * 128;

    if (wid == 8) {
        // ------- producer: interleave A halves with early B stages -----------
        if (lane == 0) {
            // A half 0 (chunks 0,1)
            MBAR_EXPECT_TX(AF0, 65536);
            #pragma unroll
            for (int ch = 0; ch < 2; ++ch) {
                BULK_G2S(sb + A_OFF + ch * 32768,
                         &g_xhi[(mtile * 4 + ch) * 8192], 16384, AF0);
                BULK_G2S(sb + A_OFF + ch * 32768 + 16384,
                         &g_xlo[(mtile * 4 + ch) * 8192], 16384, AF0);
            }
            // B stage 0 (g=0)
            {
                MBAR_EXPECT_TX(FB[0], 32768);
                BULK_G2S(sb + B_OFF,         &g_ehi[(q * 16 + 0) * 8192], 16384, FB[0]);
                BULK_G2S(sb + B_OFF + 16384, &g_elo[(q * 16 + 0) * 8192], 16384, FB[0]);
            }
            // A half 1 (chunks 2,3)
            MBAR_EXPECT_TX(AF1, 65536);
            #pragma unroll
            for (int ch = 2; ch < 4; ++ch) {
                BULK_G2S(sb + A_OFF + ch * 32768,
                         &g_xhi[(mtile * 4 + ch) * 8192], 16384, AF1);
                BULK_G2S(sb + A_OFF + ch * 32768 + 16384,
                         &g_xlo[(mtile * 4 + ch) * 8192], 16384, AF1);
            }
            // remaining B stream (g = 1..15)
            #pragma unroll 1
            for (int g = 1; g < 16; ++g) {
                int s = g % 3;
                if (g >= 3) MBAR_WAIT(EB[s], ((g / 3) + 1) & 1);
                uint32_t st = sb + B_OFF + s * 32768;
                MBAR_EXPECT_TX(FB[s], 32768);
                BULK_G2S(st,         &g_ehi[(q * 16 + g) * 8192], 16384, FB[s]);
                BULK_G2S(st + 16384, &g_elo[(q * 16 + g) * 8192], 16384, FB[s]);
            }
        }
    } else {
        // ---------------- 8 compute warps ------------------------------------
        int warp_m = wid & 3, warp_n = wid >> 2;
        int t4 = lane & 3, g4 = lane >> 2;

        float best[2][2];
        int bestI[2][2];
        #pragma unroll
        for (int a = 0; a < 2; ++a)
            #pragma unroll
            for (int b = 0; b < 2; ++b) { best[a][b] = 3.4e38f; bestI[a][b] = 0; }

        MBAR_WAIT(AF0, 0);   // first half of A (chunks 0,1)

        #pragma unroll 1
        for (int pass = 0; pass < 4; ++pass) {
            float acc[2][8][4];
            #pragma unroll
            for (int mt = 0; mt < 2; ++mt)
                #pragma unroll
                for (int nt = 0; nt < 8; ++nt)
                    #pragma unroll
                    for (int j = 0; j < 4; ++j) acc[mt][nt][j] = 0.f;

            #pragma unroll 1
            for (int ch = 0; ch < 4; ++ch) {
                int g = pass * 4 + ch;
                int s = g % 3;
                MBAR_WAIT(FB[s], (g / 3) & 1);
                if (pass == 0 && ch == 2) MBAR_WAIT(AF1, 0);  // second half of A

                const char* Ah = smem + A_OFF + ch * 32768;
                const char* Al = Ah + 16384;
                const char* Bh = smem + B_OFF + s * 32768;
                const char* Bl = Bh + 16384;

                #pragma unroll
                for (int ks = 0; ks < 4; ++ks) {
                    uint32_t ah[2][4], al[2][4];
                    #pragma unroll
                    for (int mt = 0; mt < 2; ++mt) {
                        int off = ((ks * 8 + warp_m * 2 + mt) * 32 + lane) * 16;
                        *(uint4*)ah[mt] = *(const uint4*)(Ah + off);
                        *(uint4*)al[mt] = *(const uint4*)(Al + off);
                    }
                    // paired B loads: one uint4 covers two adjacent nt
                    uint32_t bh[8][2], bl[8][2];
                    #pragma unroll
                    for (int p = 0; p < 4; ++p) {
                        int off = ((ks * 8 + warp_n * 4 + p) * 32 + lane) * 16;
                        uint4 th = *(const uint4*)(Bh + off);
                        uint4 tl_ = *(const uint4*)(Bl + off);
                        bh[2 * p][0] = th.x; bh[2 * p][1] = th.y;
                        bh[2 * p + 1][0] = th.z; bh[2 * p + 1][1] = th.w;
                        bl[2 * p][0] = tl_.x; bl[2 * p][1] = tl_.y;
                        bl[2 * p + 1][0] = tl_.z; bl[2 * p + 1][1] = tl_.w;
                    }
                    // term-ordered: hi*hi, hi*lo, lo*hi
                    #pragma unroll
                    for (int mt = 0; mt < 2; ++mt)
                        #pragma unroll
                        for (int nt = 0; nt < 8; ++nt)
                            mma_f16(acc[mt][nt], ah[mt], bh[nt]);
                    #pragma unroll
                    for (int mt = 0; mt < 2; ++mt)
                        #pragma unroll
                        for (int nt = 0; nt < 8; ++nt)
                            mma_f16(acc[mt][nt], ah[mt], bl[nt]);
                    #pragma unroll
                    for (int mt = 0; mt < 2; ++mt)
                        #pragma unroll
                        for (int nt = 0; nt < 8; ++nt)
                            mma_f16(acc[mt][nt], al[mt], bh[nt]);
                }
                if (lane == 0) MBAR_ARRIVE(EB[s]);
            }

            // fold pass into running argmin: dist = esq - 2*dot
            #pragma unroll
            for (int nt = 0; nt < 8; ++nt) {
                int clocal = pass * 128 + warp_n * 64 + nt * 8 + 2 * t4;
                float e0 = esq_s[clocal], e1 = esq_s[clocal + 1];
                int cbase = q * 512 + clocal;
                #pragma unroll
                for (int mt = 0; mt < 2; ++mt) {
                    float d0v = fmaf(-2.f, acc[mt][nt][0], e0);
                    if (d0v < best[mt][0]) { best[mt][0] = d0v; bestI[mt][0] = cbase; }
                    float d1v = fmaf(-2.f, acc[mt][nt][1], e1);
                    if (d1v < best[mt][0]) { best[mt][0] = d1v; bestI[mt][0] = cbase + 1; }
                    float d2v = fmaf(-2.f, acc[mt][nt][2], e0);
                    if (d2v < best[mt][1]) { best[mt][1] = d2v; bestI[mt][1] = cbase; }
                    float d3v = fmaf(-2.f, acc[mt][nt][3], e1);
                    if (d3v < best[mt][1]) { best[mt][1] = d3v; bestI[mt][1] = cbase + 1; }
                }
            }
        }

        // width-4 shuffle reduce, then global atomic merge
        #pragma unroll
        for (int mt = 0; mt < 2; ++mt)
            #pragma unroll
            for (int h = 0; h < 2; ++h) {
                float b = best[mt][h];
                int bi = bestI[mt][h];
                #pragma unroll
                for (int off = 2; off > 0; off >>= 1) {
                    float ob = __shfl_down_sync(0xffffffffu, b, off, 4);
                    int obi = __shfl_down_sync(0xffffffffu, bi, off, 4);
                    if (ob < b || (ob == b && obi < bi)) { b = ob; bi = obi; }
                }
                if (t4 == 0) {
                    int tok = row0 + warp_m * 32 + mt * 16 + g4 + 8 * h;
                    unsigned long long key =
                        ((unsigned long long)fmono(b) << 32) | (uint32_t)bi;
                    atomicMin(&g_key[tok], key);
                }
            }
    }
}

// ---------------------------------------------------------------------------
// gather: two (token, float4 chunk) elements per thread (ILP 2).
// 4096 CTAs x 256 threads.
// ---------------------------------------------------------------------------
__global__ void __launch_bounds__(256) gather_kernel(float* __restrict__ out, int N) {
    int i0 = blockIdx.x * 512 + threadIdx.x;
    int i1 = i0 + 256;
    int tok0 = i0 >> 6, c40 = i0 & 63;
    int tok1 = i1 >> 6, c41 = i1 & 63;
    int idx0 = (int)(g_key[tok0] & 0xFFFFFFFFull);
    int idx1 = (int)(g_key[tok1] & 0xFFFFFFFFull);
    float4 v0 = ((const float4*)g_embed)[(size_t)idx0 * 64 + c40];
    float4 v1 = ((const float4*)g_embed)[(size_t)idx1 * 64 + c41];
    ((float4*)out)[i0] = v0;
    ((float4*)out)[i1] = v1;
    if (c40 == 0) out[(size_t)N * D_DIM + tok0] = (float)idx0;
    if (c41 == 0) out[(size_t)N * D_DIM + tok1] = (float)idx1;
}

// ---------------------------------------------------------------------------
extern "C" void kernel_launch(void* const* d_in, const int* in_sizes, int n_in,
                              void* d_out, int out_size) {
    const float* X  = (const float*)d_in[0];
    const float* ES = (const float*)d_in[1];
    const float* U  = (const float*)d_in[2];
    float* out = (float*)d_out;
    (void)n_in; (void)out_size;
    int N = in_sizes[0] / D_DIM;   // 32768

    cudaFuncSetAttribute(argmin_mma_kernel,
                         cudaFuncAttributeMaxDynamicSharedMemorySize, SMEM_TOTAL);

    prep_all_kernel<<<N_CODE / 2 + (N / 128) * 16, 256>>>(X, ES, U);
    argmin_mma_kernel<<<(N / 128) * 4, 288, SMEM_TOTAL>>>();
    gather_kernel<<<(N * 64) / 512, 256>>>(out, N);
}